// round 4
// baseline (speedup 1.0000x reference)
#include <cuda_runtime.h>
#include <cuda_bf16.h>

// Problem constants (fixed by dataset)
#define NN 50000
#define EE 800000
#define IND 128
#define ADDD 8
#define HID 256
#define OUTD 128

// Scratch (device globals; no allocation allowed)
__device__ float g_h1[NN * HID];     // layer1 linear output
__device__ float g_o1[NN * HID];     // layer1 aggregated (then prelu'd)
__device__ float g_h2[NN * OUTD];    // layer2 linear output
__device__ float g_dinv[NN];
__device__ int   g_deg[NN];
__device__ int   g_src[EE];
__device__ int   g_dst[EE];
__device__ float g_norm[EE];
__device__ int   g_is64;             // 1 if edge_index is int64, 0 if int32

// ---------------------------------------------------------------------------
// Detect edge_index dtype: int64 data viewed as int32 = [lo,0,lo,0,...]
// (indices < 2^31, nonnegative). If the first 512 odd words are all zero,
// it's int64. One block, deterministic.
// ---------------------------------------------------------------------------
__global__ void k_detect(const int* __restrict__ ei32) {
    __shared__ int nz;
    if (threadIdx.x == 0) nz = 0;
    __syncthreads();
    if (ei32[2 * threadIdx.x + 1] != 0) atomicExch(&nz, 1);
    __syncthreads();
    if (threadIdx.x == 0) g_is64 = nz ? 0 : 1;
}

// ---------------------------------------------------------------------------
// Degree / norm precompute
// ---------------------------------------------------------------------------
__global__ void k_init_deg(int n) {
    int v = blockIdx.x * blockDim.x + threadIdx.x;
    if (v < n) g_deg[v] = 1;  // self-loop
}

__device__ __forceinline__ int clampN(int v) {
    return v < 0 ? 0 : (v >= NN ? NN - 1 : v);
}

__global__ void k_count(const void* __restrict__ ei, int E) {
    int e = blockIdx.x * blockDim.x + threadIdx.x;
    if (e >= E) return;
    int s, d;
    if (g_is64) {
        const long long* p = (const long long*)ei;
        s = (int)p[e];
        d = (int)p[E + e];
    } else {
        const int* p = (const int*)ei;
        s = p[e];
        d = p[E + e];
    }
    s = clampN(s);
    d = clampN(d);
    g_src[e] = s;
    g_dst[e] = d;
    atomicAdd(&g_deg[d], 1);
}

__global__ void k_dinv(int n) {
    int v = blockIdx.x * blockDim.x + threadIdx.x;
    if (v < n) g_dinv[v] = rsqrtf((float)g_deg[v]);
}

__global__ void k_norm(int E) {
    int e = blockIdx.x * blockDim.x + threadIdx.x;
    if (e >= E) return;
    g_norm[e] = g_dinv[g_src[e]] * g_dinv[g_dst[e]];
}

// ---------------------------------------------------------------------------
// Tiled fp32 GEMM: C[M,N] = A[M,K] @ W[K,N]
// CONCAT: A columns >= lda come from idv (broadcast id vector)
// BM=128, BN=128, BK=16, 256 threads, 8x8 per thread
// ---------------------------------------------------------------------------
#define BM 128
#define BN 128
#define BKK 16

template <bool CONCAT>
__global__ __launch_bounds__(256) void gemm_k(
    const float* __restrict__ A, const float* __restrict__ W,
    const float* __restrict__ idv, float* __restrict__ C,
    int M, int N, int K, int lda)
{
    __shared__ float As[BM][BKK + 1];
    __shared__ float Bs[BKK][BN];

    int tid = threadIdx.x;
    int tx = tid % 16;
    int ty = tid / 16;
    int row0 = blockIdx.x * BM;
    int col0 = blockIdx.y * BN;

    float acc[8][8] = {};

    for (int k0 = 0; k0 < K; k0 += BKK) {
        // Load A tile: 128x16 -> As[r][c]
        #pragma unroll
        for (int i = 0; i < 8; i++) {
            int r = (tid >> 4) + i * 16;
            int c = tid & 15;
            int gr = row0 + r, gk = k0 + c;
            float v = 0.f;
            if (gr < M && gk < K) {
                if (CONCAT)
                    v = (gk < lda) ? __ldg(&A[(long)gr * lda + gk]) : __ldg(&idv[gk - lda]);
                else
                    v = __ldg(&A[(long)gr * lda + gk]);
            }
            As[r][c] = v;
        }
        // Load B tile: 16x128 -> Bs[r][c]; fully coalesced
        #pragma unroll
        for (int i = 0; i < 8; i++) {
            int r = (tid >> 7) + i * 2;
            int c = tid & 127;
            int gk = k0 + r;
            Bs[r][c] = (gk < K) ? __ldg(&W[(long)gk * N + col0 + c]) : 0.f;
        }
        __syncthreads();

        #pragma unroll
        for (int kk = 0; kk < BKK; kk++) {
            float ra[8];
            #pragma unroll
            for (int i = 0; i < 8; i++) ra[i] = As[ty * 8 + i][kk];
            float4 rb0 = *(const float4*)&Bs[kk][tx * 8];
            float4 rb1 = *(const float4*)&Bs[kk][tx * 8 + 4];
            float rb[8] = {rb0.x, rb0.y, rb0.z, rb0.w, rb1.x, rb1.y, rb1.z, rb1.w};
            #pragma unroll
            for (int i = 0; i < 8; i++)
                #pragma unroll
                for (int j = 0; j < 8; j++)
                    acc[i][j] += ra[i] * rb[j];
        }
        __syncthreads();
    }

    #pragma unroll
    for (int i = 0; i < 8; i++) {
        int gr = row0 + ty * 8 + i;
        if (gr >= M) continue;
        float* cp = &C[(long)gr * N + col0 + tx * 8];
        float4 s0 = {acc[i][0], acc[i][1], acc[i][2], acc[i][3]};
        float4 s1 = {acc[i][4], acc[i][5], acc[i][6], acc[i][7]};
        *(float4*)cp = s0;
        *(float4*)(cp + 4) = s1;
    }
}

// ---------------------------------------------------------------------------
// Self-loop init: out[v*F+f] = dinv[v]^2 * h[v*F+f]
// ---------------------------------------------------------------------------
template <int LOGF>
__global__ void selfinit_k(const float* __restrict__ h, float* __restrict__ out, int total) {
    int i = blockIdx.x * blockDim.x + threadIdx.x;
    if (i >= total) return;
    float di = g_dinv[i >> LOGF];
    out[i] = di * di * h[i];
}

// ---------------------------------------------------------------------------
// Edge scatter: out[dst] += h[src] * norm  (vectorized red.v4, 2 chunks/thread)
// LOGC: log2(F/8). One thread per (edge, 8 features).
// ---------------------------------------------------------------------------
template <int LOGC>
__global__ void scatter_k(const float* __restrict__ h, float* __restrict__ out, int total) {
    int i = blockIdx.x * blockDim.x + threadIdx.x;
    if (i >= total) return;
    int e = i >> LOGC;
    int f = (i & ((1 << LOGC) - 1)) << 3;          // 8 floats per thread
    int s = __ldg(&g_src[e]);
    int d = __ldg(&g_dst[e]);
    float nrm = __ldg(&g_norm[e]);
    const float* hp = &h[((long)s << (LOGC + 3)) + f];
    float* p = &out[((long)d << (LOGC + 3)) + f];
    float4 v0 = __ldg((const float4*)hp);
    float4 v1 = __ldg((const float4*)(hp + 4));
    v0.x *= nrm; v0.y *= nrm; v0.z *= nrm; v0.w *= nrm;
    v1.x *= nrm; v1.y *= nrm; v1.z *= nrm; v1.w *= nrm;
    asm volatile("red.global.add.v4.f32 [%0], {%1, %2, %3, %4};"
                 :: "l"(p), "f"(v0.x), "f"(v0.y), "f"(v0.z), "f"(v0.w)
                 : "memory");
    asm volatile("red.global.add.v4.f32 [%0], {%1, %2, %3, %4};"
                 :: "l"(p + 4), "f"(v1.x), "f"(v1.y), "f"(v1.z), "f"(v1.w)
                 : "memory");
}

// ---------------------------------------------------------------------------
// Fused bias + PReLU (in place)
// ---------------------------------------------------------------------------
__global__ void bias_prelu_k(float* __restrict__ x, const float* __restrict__ b,
                             const float* __restrict__ a, int total, int fmask) {
    int i = blockIdx.x * blockDim.x + threadIdx.x;
    if (i >= total) return;
    int f = i & fmask;
    float v = x[i] + b[f];
    x[i] = (v >= 0.f) ? v : a[f] * v;
}

// ---------------------------------------------------------------------------
extern "C" void kernel_launch(void* const* d_in, const int* in_sizes, int n_in,
                              void* d_out, int out_size) {
    const float* x   = (const float*)d_in[0];
    const void*  ei  = d_in[1];                 // int32 or int64, detected on device
    const float* idv = (const float*)d_in[2];
    const float* W1  = (const float*)d_in[3];
    const float* b1  = (const float*)d_in[4];
    const float* a1  = (const float*)d_in[5];
    const float* W2  = (const float*)d_in[6];
    const float* b2  = (const float*)d_in[7];
    const float* a2  = (const float*)d_in[8];
    float* out = (float*)d_out;

    const int N = NN, E = EE;

    float *h1, *o1, *h2;
    cudaGetSymbolAddress((void**)&h1, g_h1);
    cudaGetSymbolAddress((void**)&o1, g_o1);
    cudaGetSymbolAddress((void**)&h2, g_h2);

    // ---- dtype detect + degree / norm precompute ----
    k_detect<<<1, 256>>>((const int*)ei);
    k_init_deg<<<(N + 255) / 256, 256>>>(N);
    k_count<<<(E + 255) / 256, 256>>>(ei, E);
    k_dinv<<<(N + 255) / 256, 256>>>(N);
    k_norm<<<(E + 255) / 256, 256>>>(E);

    // ---- layer 1: h1 = [x|id] @ W1 ----
    {
        dim3 grid((N + BM - 1) / BM, HID / BN);
        gemm_k<true><<<grid, 256>>>(x, W1, idv, h1, N, HID, IND + ADDD, IND);
    }
    {
        int total = N * HID;
        selfinit_k<8><<<(total + 255) / 256, 256>>>(h1, o1, total);
    }
    {
        int total = E * (HID / 8);
        scatter_k<5><<<(total + 511) / 512, 512>>>(h1, o1, total);
    }
    {
        int total = N * HID;
        bias_prelu_k<<<(total + 255) / 256, 256>>>(o1, b1, a1, total, HID - 1);
    }

    // ---- layer 2: h2 = o1 @ W2 ----
    {
        dim3 grid((N + BM - 1) / BM, OUTD / BN);
        gemm_k<false><<<grid, 256>>>(o1, W2, nullptr, h2, N, OUTD, HID, HID);
    }
    {
        int total = N * OUTD;
        selfinit_k<7><<<(total + 255) / 256, 256>>>(h2, out, total);
    }
    {
        int total = E * (OUTD / 8);
        scatter_k<4><<<(total + 511) / 512, 512>>>(h2, out, total);
    }
    {
        int total = N * OUTD;
        bias_prelu_k<<<(total + 255) / 256, 256>>>(out, b2, a2, total, OUTD - 1);
    }
}

// round 7
// speedup vs baseline: 1.4041x; 1.4041x over previous
#include <cuda_runtime.h>
#include <cuda_bf16.h>

// Problem constants (fixed by dataset)
#define NN 50000
#define EE 800000
#define IND 128
#define ADDD 8
#define HID 256
#define OUTD 128

// Scratch (device globals; no allocation allowed)
__device__ float g_h1[NN * HID];     // layer1 linear output
__device__ float g_o1[NN * HID];     // layer1 aggregated output
__device__ float g_h2[NN * OUTD];    // layer2 linear output
__device__ float g_dinv[NN];
__device__ int   g_deg[NN];          // 1 + in-degree
__device__ int   g_off[NN + 1];      // CSR offsets (exclusive scan of in-degree)
__device__ int   g_cur[NN];          // placement cursors
__device__ int   g_src[EE];
__device__ int   g_dst[EE];
__device__ int   g_ssrc[EE];         // CSR-sorted src
__device__ float g_snorm[EE];        // CSR-sorted edge norm
__device__ int   g_is64;             // 1 if edge_index is int64, 0 if int32

// ---------------------------------------------------------------------------
// Detect edge_index dtype: int64 data viewed as int32 = [lo,0,lo,0,...]
// ---------------------------------------------------------------------------
__global__ void k_detect(const int* __restrict__ ei32) {
    __shared__ int nz;
    if (threadIdx.x == 0) nz = 0;
    __syncthreads();
    if (ei32[2 * threadIdx.x + 1] != 0) atomicExch(&nz, 1);
    __syncthreads();
    if (threadIdx.x == 0) g_is64 = nz ? 0 : 1;
}

// ---------------------------------------------------------------------------
// Init degree (self-loop = 1) and cursor
// ---------------------------------------------------------------------------
__global__ void k_init_deg(int n) {
    int v = blockIdx.x * blockDim.x + threadIdx.x;
    if (v < n) { g_deg[v] = 1; g_cur[v] = 0; }
}

__device__ __forceinline__ int clampN(int v) {
    return v < 0 ? 0 : (v >= NN ? NN - 1 : v);
}

__global__ void k_count(const void* __restrict__ ei, int E) {
    int e = blockIdx.x * blockDim.x + threadIdx.x;
    if (e >= E) return;
    int s, d;
    if (g_is64) {
        const long long* p = (const long long*)ei;
        s = (int)p[e];
        d = (int)p[E + e];
    } else {
        const int* p = (const int*)ei;
        s = p[e];
        d = p[E + e];
    }
    s = clampN(s);
    d = clampN(d);
    g_src[e] = s;
    g_dst[e] = d;
    atomicAdd(&g_deg[d], 1);
}

__global__ void k_dinv(int n) {
    int v = blockIdx.x * blockDim.x + threadIdx.x;
    if (v < n) g_dinv[v] = rsqrtf((float)g_deg[v]);
}

// ---------------------------------------------------------------------------
// Exclusive scan of in-degree (deg-1) -> g_off.  Single block, 1024 threads.
// ---------------------------------------------------------------------------
__global__ __launch_bounds__(1024) void k_scan() {
    __shared__ int warp_sums[32];
    __shared__ int carry_s;
    int tid = threadIdx.x;
    int lane = tid & 31;
    int wid = tid >> 5;
    if (tid == 0) carry_s = 0;
    __syncthreads();
    for (int base = 0; base < NN; base += 1024) {
        int i = base + tid;
        int v = (i < NN) ? (g_deg[i] - 1) : 0;
        // warp inclusive scan
        int x = v;
        #pragma unroll
        for (int o = 1; o < 32; o <<= 1) {
            int y = __shfl_up_sync(0xFFFFFFFFu, x, o);
            if (lane >= o) x += y;
        }
        if (lane == 31) warp_sums[wid] = x;
        __syncthreads();
        if (tid < 32) {
            int s = warp_sums[tid];
            #pragma unroll
            for (int o = 1; o < 32; o <<= 1) {
                int y = __shfl_up_sync(0xFFFFFFFFu, s, o);
                if (tid >= o) s += y;
            }
            warp_sums[tid] = s;
        }
        __syncthreads();
        int incl = x + (wid > 0 ? warp_sums[wid - 1] : 0);
        int carry = carry_s;
        if (i < NN) g_off[i] = carry + incl - v;   // exclusive
        __syncthreads();
        if (tid == 1023) carry_s = carry + warp_sums[31];
        __syncthreads();
    }
    if (tid == 0) g_off[NN] = carry_s;
}

// ---------------------------------------------------------------------------
// Place edges into CSR slots; compute norm on the fly
// ---------------------------------------------------------------------------
__global__ void k_place(int E) {
    int e = blockIdx.x * blockDim.x + threadIdx.x;
    if (e >= E) return;
    int s = g_src[e];
    int d = g_dst[e];
    int pos = g_off[d] + atomicAdd(&g_cur[d], 1);
    g_ssrc[pos] = s;
    g_snorm[pos] = g_dinv[s] * g_dinv[d];
}

// ---------------------------------------------------------------------------
// Tiled fp32 GEMM: C[M,N] = A[M,K] @ W[K,N]
// ---------------------------------------------------------------------------
#define BM 128
#define BN 128
#define BKK 16

template <bool CONCAT>
__global__ __launch_bounds__(256) void gemm_k(
    const float* __restrict__ A, const float* __restrict__ W,
    const float* __restrict__ idv, float* __restrict__ C,
    int M, int N, int K, int lda)
{
    __shared__ float As[BM][BKK + 1];
    __shared__ float Bs[BKK][BN];

    int tid = threadIdx.x;
    int tx = tid % 16;
    int ty = tid / 16;
    int row0 = blockIdx.x * BM;
    int col0 = blockIdx.y * BN;

    float acc[8][8] = {};

    for (int k0 = 0; k0 < K; k0 += BKK) {
        #pragma unroll
        for (int i = 0; i < 8; i++) {
            int r = (tid >> 4) + i * 16;
            int c = tid & 15;
            int gr = row0 + r, gk = k0 + c;
            float v = 0.f;
            if (gr < M && gk < K) {
                if (CONCAT)
                    v = (gk < lda) ? __ldg(&A[(long)gr * lda + gk]) : __ldg(&idv[gk - lda]);
                else
                    v = __ldg(&A[(long)gr * lda + gk]);
            }
            As[r][c] = v;
        }
        #pragma unroll
        for (int i = 0; i < 8; i++) {
            int r = (tid >> 7) + i * 2;
            int c = tid & 127;
            int gk = k0 + r;
            Bs[r][c] = (gk < K) ? __ldg(&W[(long)gk * N + col0 + c]) : 0.f;
        }
        __syncthreads();

        #pragma unroll
        for (int kk = 0; kk < BKK; kk++) {
            float ra[8];
            #pragma unroll
            for (int i = 0; i < 8; i++) ra[i] = As[ty * 8 + i][kk];
            float4 rb0 = *(const float4*)&Bs[kk][tx * 8];
            float4 rb1 = *(const float4*)&Bs[kk][tx * 8 + 4];
            float rb[8] = {rb0.x, rb0.y, rb0.z, rb0.w, rb1.x, rb1.y, rb1.z, rb1.w};
            #pragma unroll
            for (int i = 0; i < 8; i++)
                #pragma unroll
                for (int j = 0; j < 8; j++)
                    acc[i][j] += ra[i] * rb[j];
        }
        __syncthreads();
    }

    #pragma unroll
    for (int i = 0; i < 8; i++) {
        int gr = row0 + ty * 8 + i;
        if (gr >= M) continue;
        float* cp = &C[(long)gr * N + col0 + tx * 8];
        float4 s0 = {acc[i][0], acc[i][1], acc[i][2], acc[i][3]};
        float4 s1 = {acc[i][4], acc[i][5], acc[i][6], acc[i][7]};
        *(float4*)cp = s0;
        *(float4*)(cp + 4) = s1;
    }
}

// ---------------------------------------------------------------------------
// CSR aggregation + fused epilogue:
//   out[v] = prelu( dinv[v]^2*h[v] + sum_in( norm*h[src] ) + bias )
// One node per block, F threads (F = 256 or 128), thread = feature.
// ---------------------------------------------------------------------------
template <int F>
__global__ __launch_bounds__(F) void agg_k(
    const float* __restrict__ h, const float* __restrict__ b,
    const float* __restrict__ a, float* __restrict__ out)
{
    int v = blockIdx.x;
    int f = threadIdx.x;
    int beg = g_off[v];
    int end = g_off[v + 1];
    float di = g_dinv[v];
    float bias = __ldg(&b[f]);
    float slope = __ldg(&a[f]);
    float acc = di * di * __ldg(&h[(long)v * F + f]);

    int i = beg;
    for (; i + 1 < end; i += 2) {
        int s0 = __ldg(&g_ssrc[i]);
        int s1 = __ldg(&g_ssrc[i + 1]);
        float n0 = __ldg(&g_snorm[i]);
        float n1 = __ldg(&g_snorm[i + 1]);
        float x0 = __ldg(&h[(long)s0 * F + f]);
        float x1 = __ldg(&h[(long)s1 * F + f]);
        acc += n0 * x0;
        acc += n1 * x1;
    }
    if (i < end) {
        int s0 = __ldg(&g_ssrc[i]);
        float n0 = __ldg(&g_snorm[i]);
        acc += n0 * __ldg(&h[(long)s0 * F + f]);
    }

    float val = acc + bias;
    out[(long)v * F + f] = (val >= 0.f) ? val : slope * val;
}

// ---------------------------------------------------------------------------
extern "C" void kernel_launch(void* const* d_in, const int* in_sizes, int n_in,
                              void* d_out, int out_size) {
    const float* x   = (const float*)d_in[0];
    const void*  ei  = d_in[1];                 // int32 or int64, detected on device
    const float* idv = (const float*)d_in[2];
    const float* W1  = (const float*)d_in[3];
    const float* b1  = (const float*)d_in[4];
    const float* a1  = (const float*)d_in[5];
    const float* W2  = (const float*)d_in[6];
    const float* b2  = (const float*)d_in[7];
    const float* a2  = (const float*)d_in[8];
    float* out = (float*)d_out;

    const int N = NN, E = EE;

    float *h1, *o1, *h2;
    cudaGetSymbolAddress((void**)&h1, g_h1);
    cudaGetSymbolAddress((void**)&o1, g_o1);
    cudaGetSymbolAddress((void**)&h2, g_h2);

    // ---- dtype detect + degree / CSR build ----
    k_detect<<<1, 256>>>((const int*)ei);
    k_init_deg<<<(N + 255) / 256, 256>>>(N);
    k_count<<<(E + 255) / 256, 256>>>(ei, E);
    k_dinv<<<(N + 255) / 256, 256>>>(N);
    k_scan<<<1, 1024>>>();
    k_place<<<(E + 255) / 256, 256>>>(E);

    // ---- layer 1: h1 = [x|id] @ W1 ; o1 = prelu(agg(h1) + b1) ----
    {
        dim3 grid((N + BM - 1) / BM, HID / BN);
        gemm_k<true><<<grid, 256>>>(x, W1, idv, h1, N, HID, IND + ADDD, IND);
    }
    agg_k<HID><<<N, HID>>>(h1, b1, a1, o1);

    // ---- layer 2: h2 = o1 @ W2 ; out = prelu(agg(h2) + b2) ----
    {
        dim3 grid((N + BM - 1) / BM, OUTD / BN);
        gemm_k<false><<<grid, 256>>>(o1, W2, nullptr, h2, N, OUTD, HID, HID);
    }
    agg_k<OUTD><<<N, OUTD>>>(h2, b2, a2, out);
}

// round 8
// speedup vs baseline: 1.7915x; 1.2759x over previous
#include <cuda_runtime.h>
#include <cuda_bf16.h>

// Problem constants (fixed by dataset)
#define NN 50000
#define EE 800000
#define IND 128
#define ADDD 8
#define KP 144               // padded K for layer-1 GEMM (136 -> 144)
#define HID 256
#define OUTD 128

// Scratch (device globals; no allocation allowed)
__device__ float g_ag[NN * KP];      // aggregated input [aggx | s*id | 0pad]
__device__ float g_o1[NN * HID];     // layer1 output (post bias+prelu)
__device__ float g_h2[NN * OUTD];    // layer2 linear output
__device__ float g_W1p[KP * HID];    // W1 padded to 144 rows
__device__ float g_dinv[NN];
__device__ float g_srow[NN];         // dinv^2 + sum(norm) per node
__device__ int   g_deg[NN];          // 1 + in-degree
__device__ int   g_off[NN + 1];      // CSR offsets
__device__ int   g_cur[NN];          // placement cursors
__device__ int   g_src[EE];
__device__ int   g_dst[EE];
__device__ int   g_ssrc[EE];         // CSR-sorted src
__device__ float g_snorm[EE];        // CSR-sorted edge norm
__device__ int   g_is64;             // 1 if edge_index is int64

// ---------------------------------------------------------------------------
__global__ void k_detect(const int* __restrict__ ei32) {
    __shared__ int nz;
    if (threadIdx.x == 0) nz = 0;
    __syncthreads();
    if (ei32[2 * threadIdx.x + 1] != 0) atomicExch(&nz, 1);
    __syncthreads();
    if (threadIdx.x == 0) g_is64 = nz ? 0 : 1;
}

__global__ void k_init_deg(int n) {
    int v = blockIdx.x * blockDim.x + threadIdx.x;
    if (v < n) { g_deg[v] = 1; g_cur[v] = 0; }
}

__device__ __forceinline__ int clampN(int v) {
    return v < 0 ? 0 : (v >= NN ? NN - 1 : v);
}

__global__ void k_count(const void* __restrict__ ei, int E) {
    int e = blockIdx.x * blockDim.x + threadIdx.x;
    if (e >= E) return;
    int s, d;
    if (g_is64) {
        const long long* p = (const long long*)ei;
        s = (int)p[e];
        d = (int)p[E + e];
    } else {
        const int* p = (const int*)ei;
        s = p[e];
        d = p[E + e];
    }
    s = clampN(s);
    d = clampN(d);
    g_src[e] = s;
    g_dst[e] = d;
    atomicAdd(&g_deg[d], 1);
}

__global__ void k_dinv(int n) {
    int v = blockIdx.x * blockDim.x + threadIdx.x;
    if (v < n) g_dinv[v] = rsqrtf((float)g_deg[v]);
}

// Exclusive scan of in-degree (deg-1) -> g_off.  Single block, 1024 threads.
__global__ __launch_bounds__(1024) void k_scan() {
    __shared__ int warp_sums[32];
    __shared__ int carry_s;
    int tid = threadIdx.x;
    int lane = tid & 31;
    int wid = tid >> 5;
    if (tid == 0) carry_s = 0;
    __syncthreads();
    for (int base = 0; base < NN; base += 1024) {
        int i = base + tid;
        int v = (i < NN) ? (g_deg[i] - 1) : 0;
        int x = v;
        #pragma unroll
        for (int o = 1; o < 32; o <<= 1) {
            int y = __shfl_up_sync(0xFFFFFFFFu, x, o);
            if (lane >= o) x += y;
        }
        if (lane == 31) warp_sums[wid] = x;
        __syncthreads();
        if (tid < 32) {
            int s = warp_sums[tid];
            #pragma unroll
            for (int o = 1; o < 32; o <<= 1) {
                int y = __shfl_up_sync(0xFFFFFFFFu, s, o);
                if (tid >= o) s += y;
            }
            warp_sums[tid] = s;
        }
        __syncthreads();
        int incl = x + (wid > 0 ? warp_sums[wid - 1] : 0);
        int carry = carry_s;
        if (i < NN) g_off[i] = carry + incl - v;
        __syncthreads();
        if (tid == 1023) carry_s = carry + warp_sums[31];
        __syncthreads();
    }
    if (tid == 0) g_off[NN] = carry_s;
}

__global__ void k_place(int E) {
    int e = blockIdx.x * blockDim.x + threadIdx.x;
    if (e >= E) return;
    int s = g_src[e];
    int d = g_dst[e];
    int pos = g_off[d] + atomicAdd(&g_cur[d], 1);
    g_ssrc[pos] = s;
    g_snorm[pos] = g_dinv[s] * g_dinv[d];
}

// Per-node scalar: s_v = dinv^2 + sum of incoming edge norms
__global__ void k_srow(int n) {
    int v = blockIdx.x * blockDim.x + threadIdx.x;
    if (v >= n) return;
    float s = g_dinv[v] * g_dinv[v];
    int end = g_off[v + 1];
    for (int i = g_off[v]; i < end; i++) s += g_snorm[i];
    g_srow[v] = s;
}

// Pad W1 (136 x 256) to (144 x 256) with zero rows
__global__ void k_padW1(const float* __restrict__ W1) {
    int i = blockIdx.x * blockDim.x + threadIdx.x;
    if (i >= KP * HID) return;
    int r = i >> 8;
    g_W1p[i] = (r < IND + ADDD) ? W1[i] : 0.f;
}

// ---------------------------------------------------------------------------
// Aggregate raw input x (128-dim) + id columns into padded AG [NN x 144]
// Block = 144 threads: f<128 aggregate x; 128<=f<136 = s_v*id; else 0.
// ---------------------------------------------------------------------------
__global__ __launch_bounds__(KP) void k_aggx(
    const float* __restrict__ x, const float* __restrict__ idv,
    float* __restrict__ AG)
{
    int v = blockIdx.x;
    int f = threadIdx.x;
    if (f >= IND) {
        float val = (f < IND + ADDD) ? g_srow[v] * __ldg(&idv[f - IND]) : 0.f;
        AG[(long)v * KP + f] = val;
        return;
    }
    int beg = g_off[v];
    int end = g_off[v + 1];
    float di = g_dinv[v];
    float acc = di * di * __ldg(&x[(long)v * IND + f]);
    int i = beg;
    for (; i + 1 < end; i += 2) {
        int s0 = __ldg(&g_ssrc[i]);
        int s1 = __ldg(&g_ssrc[i + 1]);
        float n0 = __ldg(&g_snorm[i]);
        float n1 = __ldg(&g_snorm[i + 1]);
        acc += n0 * __ldg(&x[(long)s0 * IND + f]);
        acc += n1 * __ldg(&x[(long)s1 * IND + f]);
    }
    if (i < end) {
        int s0 = __ldg(&g_ssrc[i]);
        acc += __ldg(&g_snorm[i]) * __ldg(&x[(long)s0 * IND + f]);
    }
    AG[(long)v * KP + f] = acc;
}

// ---------------------------------------------------------------------------
// Tiled fp32 GEMM: C = A[M,K] @ W[K,N], K multiple of 16, N multiple of 128.
// EPI: fused bias + PReLU epilogue.
// BM=128, BN=128, BK=16, 256 threads, 8x8 per thread; float4 global loads.
// ---------------------------------------------------------------------------
#define BM 128
#define BN 128
#define BKK 16

template <bool EPI>
__global__ __launch_bounds__(256) void gemm_k(
    const float* __restrict__ A, const float* __restrict__ W,
    float* __restrict__ C, int M, int N, int K, int lda,
    const float* __restrict__ b, const float* __restrict__ a)
{
    __shared__ float As[BM][BKK + 1];
    __shared__ float Bs[BKK][BN];

    int tid = threadIdx.x;
    int tx = tid % 16;
    int ty = tid / 16;
    int row0 = blockIdx.x * BM;
    int col0 = blockIdx.y * BN;

    float acc[8][8] = {};

    for (int k0 = 0; k0 < K; k0 += BKK) {
        // A tile: 128x16 = 512 float4, 2 per thread
        #pragma unroll
        for (int i = 0; i < 2; i++) {
            int fidx = tid + i * 256;
            int r = fidx >> 2;
            int c4 = (fidx & 3) << 2;
            int gr = row0 + r;
            float4 v = make_float4(0.f, 0.f, 0.f, 0.f);
            if (gr < M) v = *(const float4*)&A[(long)gr * lda + k0 + c4];
            As[r][c4] = v.x; As[r][c4 + 1] = v.y;
            As[r][c4 + 2] = v.z; As[r][c4 + 3] = v.w;
        }
        // B tile: 16x128 = 512 float4, 2 per thread
        #pragma unroll
        for (int i = 0; i < 2; i++) {
            int fidx = tid + i * 256;
            int r = fidx >> 5;
            int c4 = (fidx & 31) << 2;
            *(float4*)&Bs[r][c4] = *(const float4*)&W[(long)(k0 + r) * N + col0 + c4];
        }
        __syncthreads();

        #pragma unroll
        for (int kk = 0; kk < BKK; kk++) {
            float ra[8];
            #pragma unroll
            for (int i = 0; i < 8; i++) ra[i] = As[ty * 8 + i][kk];
            float4 rb0 = *(const float4*)&Bs[kk][tx * 8];
            float4 rb1 = *(const float4*)&Bs[kk][tx * 8 + 4];
            float rb[8] = {rb0.x, rb0.y, rb0.z, rb0.w, rb1.x, rb1.y, rb1.z, rb1.w};
            #pragma unroll
            for (int i = 0; i < 8; i++)
                #pragma unroll
                for (int j = 0; j < 8; j++)
                    acc[i][j] += ra[i] * rb[j];
        }
        __syncthreads();
    }

    float bb[8], aa[8];
    if (EPI) {
        #pragma unroll
        for (int j = 0; j < 8; j++) {
            bb[j] = __ldg(&b[col0 + tx * 8 + j]);
            aa[j] = __ldg(&a[col0 + tx * 8 + j]);
        }
    }

    #pragma unroll
    for (int i = 0; i < 8; i++) {
        int gr = row0 + ty * 8 + i;
        if (gr >= M) continue;
        float vals[8];
        #pragma unroll
        for (int j = 0; j < 8; j++) {
            float v = acc[i][j];
            if (EPI) {
                v += bb[j];
                v = (v >= 0.f) ? v : aa[j] * v;
            }
            vals[j] = v;
        }
        float* cp = &C[(long)gr * N + col0 + tx * 8];
        *(float4*)cp = make_float4(vals[0], vals[1], vals[2], vals[3]);
        *(float4*)(cp + 4) = make_float4(vals[4], vals[5], vals[6], vals[7]);
    }
}

// ---------------------------------------------------------------------------
// CSR aggregation + fused bias/prelu epilogue (layer 2 output)
// ---------------------------------------------------------------------------
template <int F>
__global__ __launch_bounds__(F) void agg_k(
    const float* __restrict__ h, const float* __restrict__ b,
    const float* __restrict__ a, float* __restrict__ out)
{
    int v = blockIdx.x;
    int f = threadIdx.x;
    int beg = g_off[v];
    int end = g_off[v + 1];
    float di = g_dinv[v];
    float bias = __ldg(&b[f]);
    float slope = __ldg(&a[f]);
    float acc = di * di * __ldg(&h[(long)v * F + f]);

    int i = beg;
    for (; i + 1 < end; i += 2) {
        int s0 = __ldg(&g_ssrc[i]);
        int s1 = __ldg(&g_ssrc[i + 1]);
        float n0 = __ldg(&g_snorm[i]);
        float n1 = __ldg(&g_snorm[i + 1]);
        acc += n0 * __ldg(&h[(long)s0 * F + f]);
        acc += n1 * __ldg(&h[(long)s1 * F + f]);
    }
    if (i < end) {
        int s0 = __ldg(&g_ssrc[i]);
        acc += __ldg(&g_snorm[i]) * __ldg(&h[(long)s0 * F + f]);
    }

    float val = acc + bias;
    out[(long)v * F + f] = (val >= 0.f) ? val : slope * val;
}

// ---------------------------------------------------------------------------
extern "C" void kernel_launch(void* const* d_in, const int* in_sizes, int n_in,
                              void* d_out, int out_size) {
    const float* x   = (const float*)d_in[0];
    const void*  ei  = d_in[1];
    const float* idv = (const float*)d_in[2];
    const float* W1  = (const float*)d_in[3];
    const float* b1  = (const float*)d_in[4];
    const float* a1  = (const float*)d_in[5];
    const float* W2  = (const float*)d_in[6];
    const float* b2  = (const float*)d_in[7];
    const float* a2  = (const float*)d_in[8];
    float* out = (float*)d_out;

    const int N = NN, E = EE;

    float *ag, *o1, *h2, *w1p;
    cudaGetSymbolAddress((void**)&ag, g_ag);
    cudaGetSymbolAddress((void**)&o1, g_o1);
    cudaGetSymbolAddress((void**)&h2, g_h2);
    cudaGetSymbolAddress((void**)&w1p, g_W1p);

    // ---- dtype detect + CSR build ----
    k_detect<<<1, 256>>>((const int*)ei);
    k_init_deg<<<(N + 255) / 256, 256>>>(N);
    k_count<<<(E + 255) / 256, 256>>>(ei, E);
    k_dinv<<<(N + 255) / 256, 256>>>(N);
    k_scan<<<1, 1024>>>();
    k_place<<<(E + 255) / 256, 256>>>(E);
    k_srow<<<(N + 255) / 256, 256>>>(N);
    k_padW1<<<(KP * HID + 255) / 256, 256>>>(W1);

    // ---- layer 1: AG = agg([x|id]) ; o1 = prelu(AG @ W1p + b1) ----
    k_aggx<<<N, KP>>>(x, idv, ag);
    {
        dim3 grid((N + BM - 1) / BM, HID / BN);
        gemm_k<true><<<grid, 256>>>(ag, w1p, o1, N, HID, KP, KP, b1, a1);
    }

    // ---- layer 2: h2 = o1 @ W2 ; out = prelu(agg(h2) + b2) ----
    {
        dim3 grid((N + BM - 1) / BM, OUTD / BN);
        gemm_k<false><<<grid, 256>>>(o1, W2, h2, N, OUTD, HID, HID, nullptr, nullptr);
    }
    agg_k<OUTD><<<N, OUTD>>>(h2, b2, a2, out);
}

// round 13
// speedup vs baseline: 2.4210x; 1.3514x over previous
#include <cuda_runtime.h>
#include <cuda_bf16.h>
#include <cstdint>

// Problem constants (fixed by dataset)
#define NN 50000
#define EE 800000
#define IND 128
#define ADDD 8
#define KP 160               // padded K for layer-1 GEMM (136 -> 160, mult of 32)
#define HID 256
#define OUTD 128

// Scratch (device globals; no allocation allowed)
__device__ float g_ag[NN * KP];      // aggregated input [aggx | s*id | 0pad]
__device__ float g_o1[NN * HID];     // layer1 output (post bias+prelu)
__device__ float g_h2[NN * OUTD];    // layer2 linear output
__device__ float g_W1p[KP * HID];    // W1 padded to 160 rows
__device__ float g_dinv[NN];
__device__ float g_srow[NN];         // dinv^2 + sum(norm) per node
__device__ int   g_deg[NN];
__device__ int   g_off[NN + 1];
__device__ int   g_cur[NN];
__device__ int   g_src[EE];
__device__ int   g_dst[EE];
__device__ int   g_ssrc[EE];
__device__ float g_snorm[EE];
__device__ int   g_is64;

// ---------------------------------------------------------------------------
__global__ void k_detect(const int* __restrict__ ei32) {
    __shared__ int nz;
    if (threadIdx.x == 0) nz = 0;
    __syncthreads();
    if (ei32[2 * threadIdx.x + 1] != 0) atomicExch(&nz, 1);
    __syncthreads();
    if (threadIdx.x == 0) g_is64 = nz ? 0 : 1;
}

__global__ void k_init_deg(int n) {
    int v = blockIdx.x * blockDim.x + threadIdx.x;
    if (v < n) { g_deg[v] = 1; g_cur[v] = 0; }
}

__device__ __forceinline__ int clampN(int v) {
    return v < 0 ? 0 : (v >= NN ? NN - 1 : v);
}

__global__ void k_count(const void* __restrict__ ei, int E) {
    int e = blockIdx.x * blockDim.x + threadIdx.x;
    if (e >= E) return;
    int s, d;
    if (g_is64) {
        const long long* p = (const long long*)ei;
        s = (int)p[e];
        d = (int)p[E + e];
    } else {
        const int* p = (const int*)ei;
        s = p[e];
        d = p[E + e];
    }
    s = clampN(s);
    d = clampN(d);
    g_src[e] = s;
    g_dst[e] = d;
    atomicAdd(&g_deg[d], 1);
}

__global__ void k_dinv(int n) {
    int v = blockIdx.x * blockDim.x + threadIdx.x;
    if (v < n) g_dinv[v] = rsqrtf((float)g_deg[v]);
}

// Exclusive scan of in-degree (deg-1) -> g_off.  Single block, 1024 threads.
__global__ __launch_bounds__(1024) void k_scan() {
    __shared__ int warp_sums[32];
    __shared__ int carry_s;
    int tid = threadIdx.x;
    int lane = tid & 31;
    int wid = tid >> 5;
    if (tid == 0) carry_s = 0;
    __syncthreads();
    for (int base = 0; base < NN; base += 1024) {
        int i = base + tid;
        int v = (i < NN) ? (g_deg[i] - 1) : 0;
        int x = v;
        #pragma unroll
        for (int o = 1; o < 32; o <<= 1) {
            int y = __shfl_up_sync(0xFFFFFFFFu, x, o);
            if (lane >= o) x += y;
        }
        if (lane == 31) warp_sums[wid] = x;
        __syncthreads();
        if (tid < 32) {
            int s = warp_sums[tid];
            #pragma unroll
            for (int o = 1; o < 32; o <<= 1) {
                int y = __shfl_up_sync(0xFFFFFFFFu, s, o);
                if (tid >= o) s += y;
            }
            warp_sums[tid] = s;
        }
        __syncthreads();
        int incl = x + (wid > 0 ? warp_sums[wid - 1] : 0);
        int carry = carry_s;
        if (i < NN) g_off[i] = carry + incl - v;
        __syncthreads();
        if (tid == 1023) carry_s = carry + warp_sums[31];
        __syncthreads();
    }
    if (tid == 0) g_off[NN] = carry_s;
}

__global__ void k_place(int E) {
    int e = blockIdx.x * blockDim.x + threadIdx.x;
    if (e >= E) return;
    int s = g_src[e];
    int d = g_dst[e];
    int pos = g_off[d] + atomicAdd(&g_cur[d], 1);
    g_ssrc[pos] = s;
    g_snorm[pos] = g_dinv[s] * g_dinv[d];
}

__global__ void k_srow(int n) {
    int v = blockIdx.x * blockDim.x + threadIdx.x;
    if (v >= n) return;
    float s = g_dinv[v] * g_dinv[v];
    int end = g_off[v + 1];
    for (int i = g_off[v]; i < end; i++) s += g_snorm[i];
    g_srow[v] = s;
}

// Pad W1 (136 x 256) to (160 x 256) with zero rows
__global__ void k_padW1(const float* __restrict__ W1) {
    int i = blockIdx.x * blockDim.x + threadIdx.x;
    if (i >= KP * HID) return;
    int r = i >> 8;
    g_W1p[i] = (r < IND + ADDD) ? W1[i] : 0.f;
}

// ---------------------------------------------------------------------------
// Aggregate raw input x (128-dim) + id columns into padded AG [NN x 160]
// ---------------------------------------------------------------------------
__global__ __launch_bounds__(KP) void k_aggx(
    const float* __restrict__ x, const float* __restrict__ idv,
    float* __restrict__ AG)
{
    int v = blockIdx.x;
    int f = threadIdx.x;
    if (f >= IND) {
        float val = (f < IND + ADDD) ? g_srow[v] * __ldg(&idv[f - IND]) : 0.f;
        AG[(long)v * KP + f] = val;
        return;
    }
    int beg = g_off[v];
    int end = g_off[v + 1];
    float di = g_dinv[v];
    float acc = di * di * __ldg(&x[(long)v * IND + f]);
    int i = beg;
    for (; i + 1 < end; i += 2) {
        int s0 = __ldg(&g_ssrc[i]);
        int s1 = __ldg(&g_ssrc[i + 1]);
        float n0 = __ldg(&g_snorm[i]);
        float n1 = __ldg(&g_snorm[i + 1]);
        acc += n0 * __ldg(&x[(long)s0 * IND + f]);
        acc += n1 * __ldg(&x[(long)s1 * IND + f]);
    }
    if (i < end) {
        int s0 = __ldg(&g_ssrc[i]);
        acc += __ldg(&g_snorm[i]) * __ldg(&x[(long)s0 * IND + f]);
    }
    AG[(long)v * KP + f] = acc;
}

// ---------------------------------------------------------------------------
// TF32 tensor-core GEMM: C = A[M,K] @ W[K,N], K mult of 32, N mult of 128.
// mma.sync.m16n8k8.tf32. BM=128, BN=128, BK=32. 256 thr = 8 warps (4Mx2N),
// warp tile 32x64. EPI: fused bias+PReLU.
// ---------------------------------------------------------------------------
#define BM 128
#define BN 128
#define BKK 32
#define APAD 36    // A smem row stride (floats): banks (4r+c) conflict-free
#define BPAD 136   // B smem row stride (floats): banks (8k+g) conflict-free

__device__ __forceinline__ uint32_t f2tf32(float f) {
    uint32_t u;
    asm("cvt.rna.tf32.f32 %0, %1;" : "=r"(u) : "f"(f));
    return u;
}

__device__ __forceinline__ void mma_tf32(float* c, const uint32_t* a, const uint32_t* b) {
    asm volatile(
        "mma.sync.aligned.m16n8k8.row.col.f32.tf32.tf32.f32 "
        "{%0,%1,%2,%3}, {%4,%5,%6,%7}, {%8,%9}, {%0,%1,%2,%3};"
        : "+f"(c[0]), "+f"(c[1]), "+f"(c[2]), "+f"(c[3])
        : "r"(a[0]), "r"(a[1]), "r"(a[2]), "r"(a[3]), "r"(b[0]), "r"(b[1]));
}

template <bool EPI>
__global__ __launch_bounds__(256) void gemm_tc(
    const float* __restrict__ A, const float* __restrict__ W,
    float* __restrict__ C, int M, int N, int K, int lda,
    const float* __restrict__ b, const float* __restrict__ a)
{
    __shared__ uint32_t As[BM * APAD];
    __shared__ uint32_t Bs[BKK * BPAD];

    int tid = threadIdx.x;
    int lane = tid & 31;
    int wid = tid >> 5;
    int warp_m = wid & 3;        // 0..3 -> M offset warp_m*32
    int warp_n = wid >> 2;       // 0..1 -> N offset warp_n*64
    int grp = lane >> 2;         // 0..7
    int tig = lane & 3;          // 0..3
    int row0 = blockIdx.x * BM;
    int col0 = blockIdx.y * BN;

    float acc[2][8][4];
    #pragma unroll
    for (int mt = 0; mt < 2; mt++)
        #pragma unroll
        for (int nt = 0; nt < 8; nt++)
            #pragma unroll
            for (int i = 0; i < 4; i++) acc[mt][nt][i] = 0.f;

    for (int k0 = 0; k0 < K; k0 += BKK) {
        // Stage A: 128x32 floats = 1024 float4, 4 per thread
        #pragma unroll
        for (int i = 0; i < 4; i++) {
            int fidx = tid + i * 256;
            int r = fidx >> 3;
            int c4 = (fidx & 7) << 2;
            int gr = row0 + r;
            float4 v = make_float4(0.f, 0.f, 0.f, 0.f);
            if (gr < M) v = *(const float4*)&A[(long)gr * lda + k0 + c4];
            uint32_t* p = &As[r * APAD + c4];
            p[0] = f2tf32(v.x); p[1] = f2tf32(v.y);
            p[2] = f2tf32(v.z); p[3] = f2tf32(v.w);
        }
        // Stage B: 32x128 floats = 1024 float4, 4 per thread
        #pragma unroll
        for (int i = 0; i < 4; i++) {
            int fidx = tid + i * 256;
            int r = fidx >> 5;
            int c4 = (fidx & 31) << 2;
            float4 v = *(const float4*)&W[(long)(k0 + r) * N + col0 + c4];
            uint32_t* p = &Bs[r * BPAD + c4];
            p[0] = f2tf32(v.x); p[1] = f2tf32(v.y);
            p[2] = f2tf32(v.z); p[3] = f2tf32(v.w);
        }
        __syncthreads();

        #pragma unroll
        for (int kk = 0; kk < BKK; kk += 8) {
            uint32_t af[2][4];
            #pragma unroll
            for (int mt = 0; mt < 2; mt++) {
                int r0 = warp_m * 32 + mt * 16;
                af[mt][0] = As[(r0 + grp) * APAD + kk + tig];
                af[mt][1] = As[(r0 + 8 + grp) * APAD + kk + tig];
                af[mt][2] = As[(r0 + grp) * APAD + kk + 4 + tig];
                af[mt][3] = As[(r0 + 8 + grp) * APAD + kk + 4 + tig];
            }
            uint32_t bf[8][2];
            #pragma unroll
            for (int nt = 0; nt < 8; nt++) {
                int c = warp_n * 64 + nt * 8 + grp;
                bf[nt][0] = Bs[(kk + tig) * BPAD + c];
                bf[nt][1] = Bs[(kk + 4 + tig) * BPAD + c];
            }
            #pragma unroll
            for (int mt = 0; mt < 2; mt++)
                #pragma unroll
                for (int nt = 0; nt < 8; nt++)
                    mma_tf32(acc[mt][nt], af[mt], bf[nt]);
        }
        __syncthreads();
    }

    // Epilogue: c0,c1 at (row, col), (row, col+1); c2,c3 at row+8
    #pragma unroll
    for (int nt = 0; nt < 8; nt++) {
        int c = col0 + warp_n * 64 + nt * 8 + tig * 2;
        float b0 = 0.f, b1 = 0.f, s0 = 1.f, s1 = 1.f;
        if (EPI) {
            b0 = __ldg(&b[c]);     b1 = __ldg(&b[c + 1]);
            s0 = __ldg(&a[c]);     s1 = __ldg(&a[c + 1]);
        }
        #pragma unroll
        for (int mt = 0; mt < 2; mt++) {
            int r = row0 + warp_m * 32 + mt * 16 + grp;
            float v0 = acc[mt][nt][0], v1 = acc[mt][nt][1];
            float v2 = acc[mt][nt][2], v3 = acc[mt][nt][3];
            if (EPI) {
                v0 += b0; v0 = (v0 >= 0.f) ? v0 : s0 * v0;
                v1 += b1; v1 = (v1 >= 0.f) ? v1 : s1 * v1;
                v2 += b0; v2 = (v2 >= 0.f) ? v2 : s0 * v2;
                v3 += b1; v3 = (v3 >= 0.f) ? v3 : s1 * v3;
            }
            if (r < M)     *(float2*)&C[(long)r * N + c]       = make_float2(v0, v1);
            if (r + 8 < M) *(float2*)&C[(long)(r + 8) * N + c] = make_float2(v2, v3);
        }
    }
}

// ---------------------------------------------------------------------------
// CSR aggregation + fused bias/prelu epilogue (layer 2 output)
// ---------------------------------------------------------------------------
template <int F>
__global__ __launch_bounds__(F) void agg_k(
    const float* __restrict__ h, const float* __restrict__ b,
    const float* __restrict__ a, float* __restrict__ out)
{
    int v = blockIdx.x;
    int f = threadIdx.x;
    int beg = g_off[v];
    int end = g_off[v + 1];
    float di = g_dinv[v];
    float bias = __ldg(&b[f]);
    float slope = __ldg(&a[f]);
    float acc = di * di * __ldg(&h[(long)v * F + f]);

    int i = beg;
    for (; i + 1 < end; i += 2) {
        int s0 = __ldg(&g_ssrc[i]);
        int s1 = __ldg(&g_ssrc[i + 1]);
        float n0 = __ldg(&g_snorm[i]);
        float n1 = __ldg(&g_snorm[i + 1]);
        acc += n0 * __ldg(&h[(long)s0 * F + f]);
        acc += n1 * __ldg(&h[(long)s1 * F + f]);
    }
    if (i < end) {
        int s0 = __ldg(&g_ssrc[i]);
        acc += __ldg(&g_snorm[i]) * __ldg(&h[(long)s0 * F + f]);
    }

    float val = acc + bias;
    out[(long)v * F + f] = (val >= 0.f) ? val : slope * val;
}

// ---------------------------------------------------------------------------
extern "C" void kernel_launch(void* const* d_in, const int* in_sizes, int n_in,
                              void* d_out, int out_size) {
    const float* x   = (const float*)d_in[0];
    const void*  ei  = d_in[1];
    const float* idv = (const float*)d_in[2];
    const float* W1  = (const float*)d_in[3];
    const float* b1  = (const float*)d_in[4];
    const float* a1  = (const float*)d_in[5];
    const float* W2  = (const float*)d_in[6];
    const float* b2  = (const float*)d_in[7];
    const float* a2  = (const float*)d_in[8];
    float* out = (float*)d_out;

    const int N = NN, E = EE;

    float *ag, *o1, *h2, *w1p;
    cudaGetSymbolAddress((void**)&ag, g_ag);
    cudaGetSymbolAddress((void**)&o1, g_o1);
    cudaGetSymbolAddress((void**)&h2, g_h2);
    cudaGetSymbolAddress((void**)&w1p, g_W1p);

    // ---- dtype detect + CSR build ----
    k_detect<<<1, 256>>>((const int*)ei);
    k_init_deg<<<(N + 255) / 256, 256>>>(N);
    k_count<<<(E + 255) / 256, 256>>>(ei, E);
    k_dinv<<<(N + 255) / 256, 256>>>(N);
    k_scan<<<1, 1024>>>();
    k_place<<<(E + 255) / 256, 256>>>(E);
    k_srow<<<(N + 255) / 256, 256>>>(N);
    k_padW1<<<(KP * HID + 255) / 256, 256>>>(W1);

    // ---- layer 1: AG = agg([x|id]) ; o1 = prelu(AG @ W1p + b1) ----
    k_aggx<<<N, KP>>>(x, idv, ag);
    {
        dim3 grid((N + BM - 1) / BM, HID / BN);
        gemm_tc<true><<<grid, 256>>>(ag, w1p, o1, N, HID, KP, KP, b1, a1);
    }

    // ---- layer 2: h2 = o1 @ W2 ; out = prelu(agg(h2) + b2) ----
    {
        dim3 grid((N + BM - 1) / BM, OUTD / BN);
        gemm_tc<false><<<grid, 256>>>(o1, W2, h2, N, OUTD, HID, HID, nullptr, nullptr);
    }
    agg_k<OUTD><<<N, OUTD>>>(h2, b2, a2, out);
}